// round 7
// baseline (speedup 1.0000x reference)
#include <cuda_runtime.h>
#include <cuda_fp16.h>
#include <math.h>
#include <stdint.h>

#define BB 2
#define SS 2048
#define DD 1024
#define HH 16
#define GM (BB*SS)   /* 4096 */
#define GN DD
#define GK DD
#define LOSCALE 2048.0f
#define INVLOSCALE (1.0f/2048.0f)

// ---------------- scratch (allocation-free) ----------------
__device__ __half g_Xh[GM*DD],  g_Xl[GM*DD];
__device__ __half g_Qh[GM*DD],  g_Ql[GM*DD];
__device__ __half g_Kh[GM*DD],  g_Kl[GM*DD];
__device__ __half g_Vh[GM*DD],  g_Vl[GM*DD];
__device__ __half g_AOh[GM*DD], g_AOl[GM*DD];
__device__ __half g_Wqh[DD*DD], g_Wql[DD*DD];
__device__ __half g_Wkh[DD*DD], g_Wkl[DD*DD];
__device__ __half g_Wvh[DD*DD], g_Wvl[DD*DD];
__device__ __half g_Woh[DD*DD], g_Wol[DD*DD];

// ---------------- helpers ----------------
__device__ __forceinline__ uint32_t smem_u32(const void* p) {
    return (uint32_t)__cvta_generic_to_shared(p);
}
__device__ __forceinline__ void cp_async16(uint32_t dst, const void* src) {
    asm volatile("cp.async.cg.shared.global [%0], [%1], 16;" :: "r"(dst), "l"(src) : "memory");
}
__device__ __forceinline__ void cp_commit() {
    asm volatile("cp.async.commit_group;" ::: "memory");
}
template<int N>
__device__ __forceinline__ void cp_wait() {
    asm volatile("cp.async.wait_group %0;" :: "n"(N) : "memory");
}
__device__ __forceinline__ void ldm_x4(uint32_t* r, uint32_t addr) {
    asm volatile("ldmatrix.sync.aligned.m8n8.x4.shared.b16 {%0,%1,%2,%3}, [%4];"
                 : "=r"(r[0]), "=r"(r[1]), "=r"(r[2]), "=r"(r[3]) : "r"(addr));
}
__device__ __forceinline__ void ldm_x4_t(uint32_t* r, uint32_t addr) {
    asm volatile("ldmatrix.sync.aligned.m8n8.x4.trans.shared.b16 {%0,%1,%2,%3}, [%4];"
                 : "=r"(r[0]), "=r"(r[1]), "=r"(r[2]), "=r"(r[3]) : "r"(addr));
}
// f16 inputs, f32 accumulate
__device__ __forceinline__ void mma_f32acc(float* c, const uint32_t* a, const uint32_t* b) {
    asm volatile("mma.sync.aligned.m16n8k16.row.col.f32.f16.f16.f32 "
                 "{%0,%1,%2,%3}, {%4,%5,%6,%7}, {%8,%9}, {%0,%1,%2,%3};"
                 : "+f"(c[0]), "+f"(c[1]), "+f"(c[2]), "+f"(c[3])
                 : "r"(a[0]), "r"(a[1]), "r"(a[2]), "r"(a[3]), "r"(b[0]), "r"(b[1]));
}
// f16 inputs, f16 accumulate (corrections) — c[0]=(v0,v1) c[1]=(v2,v3) packed
__device__ __forceinline__ void mma_f16acc(uint32_t* c, const uint32_t* a, const uint32_t* b) {
    asm volatile("mma.sync.aligned.m16n8k16.row.col.f16.f16.f16.f16 "
                 "{%0,%1}, {%2,%3,%4,%5}, {%6,%7}, {%0,%1};"
                 : "+r"(c[0]), "+r"(c[1])
                 : "r"(a[0]), "r"(a[1]), "r"(a[2]), "r"(a[3]), "r"(b[0]), "r"(b[1]));
}
__device__ __forceinline__ uint32_t packh2(float a, float b) {
    __half2 h = __floats2half2_rn(a, b);
    return *(uint32_t*)&h;
}
__device__ __forceinline__ float2 unpackh2(uint32_t r) {
    __half2 h = *(__half2*)&r;
    return __half22float2(h);
}
__device__ __forceinline__ float warp_rmax(float x) {
    x = fmaxf(x, __shfl_xor_sync(0xffffffffu, x, 1));
    x = fmaxf(x, __shfl_xor_sync(0xffffffffu, x, 2));
    return x;
}
__device__ __forceinline__ float warp_rsum(float x) {
    x += __shfl_xor_sync(0xffffffffu, x, 1);
    x += __shfl_xor_sync(0xffffffffu, x, 2);
    return x;
}

// ---------------- split fp32 -> f16 hi + f16 lo(*2048) ----------------
__global__ void split_f16(const float* __restrict__ in, __half* __restrict__ hi,
                          __half* __restrict__ lo, int n4)
{
    int i = blockIdx.x*blockDim.x + threadIdx.x;
    int stride = gridDim.x*blockDim.x;
    const float4* in4 = (const float4*)in;
    uint32_t* h2 = (uint32_t*)hi;
    uint32_t* l2 = (uint32_t*)lo;
    for (; i < n4; i += stride) {
        float4 v = in4[i];
        uint32_t h01 = packh2(v.x, v.y), h23 = packh2(v.z, v.w);
        float2 f01 = unpackh2(h01), f23 = unpackh2(h23);
        uint32_t l01 = packh2((v.x - f01.x)*LOSCALE, (v.y - f01.y)*LOSCALE);
        uint32_t l23 = packh2((v.z - f23.x)*LOSCALE, (v.w - f23.y)*LOSCALE);
        h2[i*2] = h01; h2[i*2+1] = h23;
        l2[i*2] = l01; l2[i*2+1] = l23;
    }
}

// ---------------- f16x2 GEMM on mma.sync: C = alpha * (A @ B^T) ----------------
// Main pass f32-acc; corrections (Al'*Bh + Ah*Bl') f16-acc, merged /2048 at epilogue.
#define KCH 64
#define NCH (GK/KCH)
#define SRE 72
#define SRB (SRE*2)
#define TILE_B (128*SRB)
#define STAGE_B (4*TILE_B)          /* 73728 */
#define GEMM_SMEM (3*STAGE_B)       /* 221184 */

template<bool SPLIT>
__global__ __launch_bounds__(256, 1)
void gemm_f16x2(const __half* __restrict__ Ah, const __half* __restrict__ Al,
                const __half* __restrict__ Bh, const __half* __restrict__ Bl,
                float* __restrict__ Cf, __half* __restrict__ Chi,
                __half* __restrict__ Clo, float alpha)
{
    extern __shared__ char smem[];
    const uint32_t sb = smem_u32(smem);
    const int tid  = threadIdx.x;
    const int lane = tid & 31;
    const int warp = tid >> 5;
    const int wm   = warp & 3;
    const int wn   = warp >> 2;
    const int cRow = blockIdx.y << 7;
    const int cCol = blockIdx.x << 7;

    const __half* gsrc[4];
    gsrc[0] = Ah + (size_t)cRow*GK;
    gsrc[1] = Al + (size_t)cRow*GK;
    gsrc[2] = Bh + (size_t)cCol*GK;
    gsrc[3] = Bl + (size_t)cCol*GK;

    const int ldRow = tid >> 3;
    const int ldCol = tid & 7;

    const uint32_t aOff = (uint32_t)((lane & 15)*SRB + (lane >> 4)*16 + wm*32*SRB);
    const uint32_t bOff = (uint32_t)(((lane & 7) + ((lane >> 4) << 3))*SRB
                                     + ((lane >> 3) & 1)*16 + wn*64*SRB);

    float acc[2][8][4];
    uint32_t corr[2][8][2];
#pragma unroll
    for (int mt = 0; mt < 2; mt++)
#pragma unroll
        for (int nt = 0; nt < 8; nt++) {
#pragma unroll
            for (int q = 0; q < 4; q++) acc[mt][nt][q] = 0.f;
            corr[mt][nt][0] = 0u; corr[mt][nt][1] = 0u;
        }

    auto issue_chunk = [&](int j, int s) {
        const uint32_t st = sb + (uint32_t)s*STAGE_B;
        const int k0 = j*KCH;
#pragma unroll
        for (int t = 0; t < 4; t++)
#pragma unroll
            for (int i = 0; i < 4; i++) {
                int row = ldRow + i*32;
                cp_async16(st + t*TILE_B + row*SRB + ldCol*16,
                           gsrc[t] + (size_t)row*GK + k0 + ldCol*8);
            }
        cp_commit();
    };

    issue_chunk(0, 0);
    issue_chunk(1, 1);

    for (int j = 0; j < NCH; j++) {
        if (j + 2 < NCH) issue_chunk(j + 2, (j + 2) % 3);
        if (j + 2 < NCH)      cp_wait<2>();
        else if (j + 1 < NCH) cp_wait<1>();
        else                  cp_wait<0>();
        __syncthreads();

        const uint32_t stg = sb + (uint32_t)(j % 3)*STAGE_B;
        const uint32_t aBH = stg + aOff;
        const uint32_t aBL = stg + TILE_B + aOff;
        const uint32_t bBH = stg + 2*TILE_B + bOff;
        const uint32_t bBL = stg + 3*TILE_B + bOff;
#pragma unroll
        for (int k16 = 0; k16 < 4; k16++) {
            uint32_t ah2[2][4], al2[2][4], bh2[4][4], bl2[4][4];
            ldm_x4(ah2[0], aBH + k16*32);
            ldm_x4(ah2[1], aBH + k16*32 + 16*SRB);
            ldm_x4(al2[0], aBL + k16*32);
            ldm_x4(al2[1], aBL + k16*32 + 16*SRB);
#pragma unroll
            for (int ng = 0; ng < 4; ng++) {
                ldm_x4(bh2[ng], bBH + k16*32 + ng*16*SRB);
                ldm_x4(bl2[ng], bBL + k16*32 + ng*16*SRB);
            }
#pragma unroll
            for (int mt = 0; mt < 2; mt++)
#pragma unroll
                for (int ng = 0; ng < 4; ng++) {
                    mma_f32acc(acc[mt][2*ng+0], ah2[mt], &bh2[ng][0]);
                    mma_f32acc(acc[mt][2*ng+1], ah2[mt], &bh2[ng][2]);
                    mma_f16acc(corr[mt][2*ng+0], al2[mt], &bh2[ng][0]);
                    mma_f16acc(corr[mt][2*ng+1], al2[mt], &bh2[ng][2]);
                    mma_f16acc(corr[mt][2*ng+0], ah2[mt], &bl2[ng][0]);
                    mma_f16acc(corr[mt][2*ng+1], ah2[mt], &bl2[ng][2]);
                }
        }
        __syncthreads();
    }

    const int gid = lane >> 2, tig = lane & 3;
#pragma unroll
    for (int mt = 0; mt < 2; mt++) {
        const int m0 = cRow + wm*32 + mt*16 + gid;
#pragma unroll
        for (int nt = 0; nt < 8; nt++) {
            const int n = cCol + wn*64 + nt*8 + tig*2;
            float2 c01 = unpackh2(corr[mt][nt][0]);
            float2 c23 = unpackh2(corr[mt][nt][1]);
            float v0 = (acc[mt][nt][0] + c01.x*INVLOSCALE)*alpha;
            float v1 = (acc[mt][nt][1] + c01.y*INVLOSCALE)*alpha;
            float v2 = (acc[mt][nt][2] + c23.x*INVLOSCALE)*alpha;
            float v3 = (acc[mt][nt][3] + c23.y*INVLOSCALE)*alpha;
            if (SPLIT) {
                uint32_t h01 = packh2(v0, v1), h23 = packh2(v2, v3);
                float2 f01 = unpackh2(h01), f23 = unpackh2(h23);
                uint32_t l01 = packh2((v0 - f01.x)*LOSCALE, (v1 - f01.y)*LOSCALE);
                uint32_t l23 = packh2((v2 - f23.x)*LOSCALE, (v3 - f23.y)*LOSCALE);
                *(uint32_t*)(Chi + (size_t)m0*GN + n)     = h01;
                *(uint32_t*)(Clo + (size_t)m0*GN + n)     = l01;
                *(uint32_t*)(Chi + (size_t)(m0+8)*GN + n) = h23;
                *(uint32_t*)(Clo + (size_t)(m0+8)*GN + n) = l23;
            } else {
                float2 a0 = {v0, v1}, a1 = {v2, v3};
                *(float2*)(Cf + (size_t)m0*GN + n)     = a0;
                *(float2*)(Cf + (size_t)(m0+8)*GN + n) = a1;
            }
        }
    }
}

// ---------------------------------------------------------------------------
// Flash attention on mma.sync, causal, f16x2 split. 3-stage KV pipeline.
// Main passes f32-acc; corrections f16-acc merged per tile.
// ---------------------------------------------------------------------------
#define FQSTR 72
#define FTILE (64*FQSTR*2)
#define FSTAGE (4*FTILE)                         /* 36864 */
#define FLASH_SMEM (2*128*FQSTR*2 + 3*FSTAGE)    /* 147456 */

__global__ __launch_bounds__(256, 1)
void flash_mma(const __half* __restrict__ Qh_, const __half* __restrict__ Ql_,
               const __half* __restrict__ Kh_, const __half* __restrict__ Kl_,
               const __half* __restrict__ Vh_, const __half* __restrict__ Vl_,
               __half* __restrict__ AOh, __half* __restrict__ AOl)
{
    extern __shared__ char smc[];
    const int qt  = (int)gridDim.x - 1 - (int)blockIdx.x;
    const int h   = blockIdx.y, b = blockIdx.z;
    const int tid = threadIdx.x;
    const int lane = tid & 31, w = tid >> 5;
    const int qbase = qt*128;
    const int ktmax = 2*qt + 1;

    const uint32_t sb  = smem_u32(smc);
    const uint32_t uQh = sb;
    const uint32_t uQl = sb + 128*FQSTR*2;
    const uint32_t uKV = sb + 2*128*FQSTR*2;

    const __half* qsrc[2]  = {Qh_, Ql_};
    const __half* kvsrc[4] = {Kh_, Kl_, Vh_, Vl_};
    const size_t hofs = (size_t)h*64;

    auto load_kv = [&](int kt, int s) {
#pragma unroll
        for (int i = 0; i < 8; i++) {
            int id = tid + i*256;
            int a = id >> 9, r = (id >> 3) & 63, c = id & 7;
            const __half* g = kvsrc[a] + (size_t)(b*SS + kt*64 + r)*DD + hofs + c*8;
            cp_async16(uKV + s*FSTAGE + a*FTILE + (uint32_t)(r*FQSTR + c*8)*2, g);
        }
    };

#pragma unroll
    for (int i = 0; i < 8; i++) {
        int id = tid + i*256;
        int a = id >> 10, r = (id >> 3) & 127, c = id & 7;
        const __half* g = qsrc[a] + (size_t)(b*SS + qbase + r)*DD + hofs + c*8;
        cp_async16((a ? uQl : uQh) + (uint32_t)(r*FQSTR + c*8)*2, g);
    }
    load_kv(0, 0);
    cp_commit();
    load_kv(1, 1);
    cp_commit();

    const int gid = lane >> 2, tig = lane & 3;
    const int qrow_off = ((lane>>3)&1)*8 + (lane&7);
    const int qd_off   = (lane>>4)*8;
    const int krow_off = (lane>>4)*8 + (lane&7);
    const int kd_off   = ((lane>>3)&1)*8;
    const int vrow_off = ((lane>>3)&1)*8 + (lane&7);
    const int vd_off   = (lane>>4)*8;

    uint32_t qh[4][4], ql[4][4];

    float m0 = -INFINITY, m1 = -INFINITY, l0 = 0.f, l1 = 0.f;
    float oacc[8][4];
#pragma unroll
    for (int nt = 0; nt < 8; nt++)
#pragma unroll
        for (int q = 0; q < 4; q++) oacc[nt][q] = 0.f;

    const int row0 = qbase + 16*w + gid;
    const int row1 = row0 + 8;

    for (int kt = 0; kt <= ktmax; kt++) {
        if (kt + 2 <= ktmax) { load_kv(kt + 2, (kt + 2) % 3); cp_commit(); }
        if (kt + 2 <= ktmax)      cp_wait<2>();
        else if (kt + 1 <= ktmax) cp_wait<1>();
        else                      cp_wait<0>();
        __syncthreads();

        if (kt == 0) {
            uint32_t ah = uQh + (uint32_t)((16*w + qrow_off)*FQSTR + qd_off)*2;
            uint32_t al = uQl + (uint32_t)((16*w + qrow_off)*FQSTR + qd_off)*2;
#pragma unroll
            for (int kk = 0; kk < 4; kk++) {
                ldm_x4(qh[kk], ah + kk*32);
                ldm_x4(ql[kk], al + kk*32);
            }
        }

        const uint32_t st = uKV + (uint32_t)(kt % 3)*FSTAGE;
        const bool active = (kt*64 <= qbase + 16*w + 15);
        if (active) {
            float sacc[8][4];
            uint32_t scorr[8][2];
#pragma unroll
            for (int nt = 0; nt < 8; nt++) {
#pragma unroll
                for (int q = 0; q < 4; q++) sacc[nt][q] = 0.f;
                scorr[nt][0] = 0u; scorr[nt][1] = 0u;
            }

            // ---- S: main Qh*Kh (f32), corr Ql'*Kh + Qh*Kl' (f16) ----
#pragma unroll
            for (int kk = 0; kk < 4; kk++) {
                const uint32_t kb0 = st + (uint32_t)(krow_off*FQSTR + kd_off + 16*kk)*2;
                uint32_t kb[8][2], kl[8][2];
#pragma unroll
                for (int p = 0; p < 4; p++) {
                    uint32_t r[4];
                    ldm_x4(r, kb0 + (uint32_t)(16*p*FQSTR)*2);
                    kb[2*p][0] = r[0]; kb[2*p][1] = r[1];
                    kb[2*p+1][0] = r[2]; kb[2*p+1][1] = r[3];
                    ldm_x4(r, kb0 + FTILE + (uint32_t)(16*p*FQSTR)*2);
                    kl[2*p][0] = r[0]; kl[2*p][1] = r[1];
                    kl[2*p+1][0] = r[2]; kl[2*p+1][1] = r[3];
                }
#pragma unroll
                for (int nt = 0; nt < 8; nt++) {
                    mma_f32acc(sacc[nt], qh[kk], kb[nt]);
                    mma_f16acc(scorr[nt], ql[kk], kb[nt]);
                    mma_f16acc(scorr[nt], qh[kk], kl[nt]);
                }
            }
            // merge corrections
#pragma unroll
            for (int nt = 0; nt < 8; nt++) {
                float2 c01 = unpackh2(scorr[nt][0]);
                float2 c23 = unpackh2(scorr[nt][1]);
                sacc[nt][0] += c01.x*INVLOSCALE;
                sacc[nt][1] += c01.y*INVLOSCALE;
                sacc[nt][2] += c23.x*INVLOSCALE;
                sacc[nt][3] += c23.y*INVLOSCALE;
            }

            // ---- causal mask ----
            if (kt >= 2*qt) {
                const int colb = kt*64 + 2*tig;
#pragma unroll
                for (int nt = 0; nt < 8; nt++) {
                    int c0 = colb + 8*nt, c1 = c0 + 1;
                    if (c0 > row0) sacc[nt][0] = -1e10f;
                    if (c1 > row0) sacc[nt][1] = -1e10f;
                    if (c0 > row1) sacc[nt][2] = -1e10f;
                    if (c1 > row1) sacc[nt][3] = -1e10f;
                }
            }

            // ---- online softmax ----
            float rm0 = -INFINITY, rm1 = -INFINITY;
#pragma unroll
            for (int nt = 0; nt < 8; nt++) {
                rm0 = fmaxf(rm0, fmaxf(sacc[nt][0], sacc[nt][1]));
                rm1 = fmaxf(rm1, fmaxf(sacc[nt][2], sacc[nt][3]));
            }
            rm0 = warp_rmax(rm0); rm1 = warp_rmax(rm1);
            float mn0 = fmaxf(m0, rm0), mn1 = fmaxf(m1, rm1);
            float cr0 = __expf(m0 - mn0), cr1 = __expf(m1 - mn1);
            m0 = mn0; m1 = mn1;
            float ps0 = 0.f, ps1 = 0.f;
#pragma unroll
            for (int nt = 0; nt < 8; nt++) {
                float p0 = __expf(sacc[nt][0] - mn0);
                float p1 = __expf(sacc[nt][1] - mn0);
                float p2 = __expf(sacc[nt][2] - mn1);
                float p3 = __expf(sacc[nt][3] - mn1);
                sacc[nt][0] = p0; sacc[nt][1] = p1; sacc[nt][2] = p2; sacc[nt][3] = p3;
                ps0 += p0 + p1; ps1 += p2 + p3;
            }
            ps0 = warp_rsum(ps0); ps1 = warp_rsum(ps1);
            l0 = l0*cr0 + ps0; l1 = l1*cr1 + ps1;
#pragma unroll
            for (int nt = 0; nt < 8; nt++) {
                oacc[nt][0] *= cr0; oacc[nt][1] *= cr0;
                oacc[nt][2] *= cr1; oacc[nt][3] *= cr1;
            }

            // ---- O: main Ph*Vh (f32), corr Pl'*Vh + Ph*Vl' (f16, per tile) ----
            uint32_t ocorr[8][2];
#pragma unroll
            for (int nt = 0; nt < 8; nt++) { ocorr[nt][0] = 0u; ocorr[nt][1] = 0u; }
#pragma unroll
            for (int kk = 0; kk < 4; kk++) {
                uint32_t pah[4], pal[4];
#pragma unroll
                for (int jj = 0; jj < 2; jj++) {
                    const float* s4 = sacc[2*kk + jj];
                    uint32_t h01 = packh2(s4[0], s4[1]);
                    uint32_t h23 = packh2(s4[2], s4[3]);
                    float2 f01 = unpackh2(h01), f23 = unpackh2(h23);
                    pah[2*jj]   = h01;
                    pah[2*jj+1] = h23;
                    pal[2*jj]   = packh2((s4[0] - f01.x)*LOSCALE, (s4[1] - f01.y)*LOSCALE);
                    pal[2*jj+1] = packh2((s4[2] - f23.x)*LOSCALE, (s4[3] - f23.y)*LOSCALE);
                }
                const uint32_t vb0 = st + 2*FTILE + (uint32_t)((16*kk + vrow_off)*FQSTR + vd_off)*2;
                uint32_t vb[8][2], vl[8][2];
#pragma unroll
                for (int p = 0; p < 4; p++) {
                    uint32_t r[4];
                    ldm_x4_t(r, vb0 + (uint32_t)(16*p)*2);
                    vb[2*p][0] = r[0]; vb[2*p][1] = r[1];
                    vb[2*p+1][0] = r[2]; vb[2*p+1][1] = r[3];
                    ldm_x4_t(r, vb0 + FTILE + (uint32_t)(16*p)*2);
                    vl[2*p][0] = r[0]; vl[2*p][1] = r[1];
                    vl[2*p+1][0] = r[2]; vl[2*p+1][1] = r[3];
                }
#pragma unroll
                for (int nt = 0; nt < 8; nt++) {
                    mma_f32acc(oacc[nt], pah, vb[nt]);
                    mma_f16acc(ocorr[nt], pal, vb[nt]);
                    mma_f16acc(ocorr[nt], pah, vl[nt]);
                }
            }
#pragma unroll
            for (int nt = 0; nt < 8; nt++) {
                float2 c01 = unpackh2(ocorr[nt][0]);
                float2 c23 = unpackh2(ocorr[nt][1]);
                oacc[nt][0] += c01.x*INVLOSCALE;
                oacc[nt][1] += c01.y*INVLOSCALE;
                oacc[nt][2] += c23.x*INVLOSCALE;
                oacc[nt][3] += c23.y*INVLOSCALE;
            }
        }
        __syncthreads();
    }

    // ---- epilogue: normalize + split to f16 hi/lo(*2048) ----
    const float inv0 = 1.f / l0, inv1 = 1.f / l1;
    const size_t r0g = (size_t)(b*SS + row0);
    const size_t r1g = (size_t)(b*SS + row1);
#pragma unroll
    for (int nt = 0; nt < 8; nt++) {
        const size_t col = hofs + 8*nt + 2*tig;
        float x0 = oacc[nt][0]*inv0, x1 = oacc[nt][1]*inv0;
        float x2 = oacc[nt][2]*inv1, x3 = oacc[nt][3]*inv1;
        uint32_t h01 = packh2(x0, x1), h23 = packh2(x2, x3);
        float2 f01 = unpackh2(h01), f23 = unpackh2(h23);
        uint32_t l01 = packh2((x0 - f01.x)*LOSCALE, (x1 - f01.y)*LOSCALE);
        uint32_t l23 = packh2((x2 - f23.x)*LOSCALE, (x3 - f23.y)*LOSCALE);
        *(uint32_t*)(AOh + r0g*DD + col) = h01;
        *(uint32_t*)(AOl + r0g*DD + col) = l01;
        *(uint32_t*)(AOh + r1g*DD + col) = h23;
        *(uint32_t*)(AOl + r1g*DD + col) = l23;
    }
}

// ---------------------------------------------------------------------------
extern "C" void kernel_launch(void* const* d_in, const int* in_sizes, int n_in,
                              void* d_out, int out_size)
{
    (void)in_sizes; (void)n_in; (void)out_size;
    const float* X  = (const float*)d_in[0];
    const float* Wq = (const float*)d_in[1];
    const float* Wk = (const float*)d_in[2];
    const float* Wv = (const float*)d_in[3];
    const float* Wo = (const float*)d_in[4];
    float* out = (float*)d_out;

    __half *Xh, *Xl, *Qh, *Ql, *Kh, *Kl, *Vh, *Vl, *AOh, *AOl;
    __half *Wqh, *Wql, *Wkh, *Wkl, *Wvh, *Wvl, *Woh, *Wol;
    cudaGetSymbolAddress((void**)&Xh,  g_Xh);
    cudaGetSymbolAddress((void**)&Xl,  g_Xl);
    cudaGetSymbolAddress((void**)&Qh,  g_Qh);
    cudaGetSymbolAddress((void**)&Ql,  g_Ql);
    cudaGetSymbolAddress((void**)&Kh,  g_Kh);
    cudaGetSymbolAddress((void**)&Kl,  g_Kl);
    cudaGetSymbolAddress((void**)&Vh,  g_Vh);
    cudaGetSymbolAddress((void**)&Vl,  g_Vl);
    cudaGetSymbolAddress((void**)&AOh, g_AOh);
    cudaGetSymbolAddress((void**)&AOl, g_AOl);
    cudaGetSymbolAddress((void**)&Wqh, g_Wqh);
    cudaGetSymbolAddress((void**)&Wql, g_Wql);
    cudaGetSymbolAddress((void**)&Wkh, g_Wkh);
    cudaGetSymbolAddress((void**)&Wkl, g_Wkl);
    cudaGetSymbolAddress((void**)&Wvh, g_Wvh);
    cudaGetSymbolAddress((void**)&Wvl, g_Wvl);
    cudaGetSymbolAddress((void**)&Woh, g_Woh);
    cudaGetSymbolAddress((void**)&Wol, g_Wol);

    cudaFuncSetAttribute(gemm_f16x2<true>,  cudaFuncAttributeMaxDynamicSharedMemorySize, GEMM_SMEM);
    cudaFuncSetAttribute(gemm_f16x2<false>, cudaFuncAttributeMaxDynamicSharedMemorySize, GEMM_SMEM);
    cudaFuncSetAttribute(flash_mma, cudaFuncAttributeMaxDynamicSharedMemorySize, FLASH_SMEM);

    split_f16<<<512, 256>>>(X,  Xh,  Xl,  GM*DD/4);
    split_f16<<<256, 256>>>(Wq, Wqh, Wql, DD*DD/4);
    split_f16<<<256, 256>>>(Wk, Wkh, Wkl, DD*DD/4);
    split_f16<<<256, 256>>>(Wv, Wvh, Wvl, DD*DD/4);
    split_f16<<<256, 256>>>(Wo, Woh, Wol, DD*DD/4);

    dim3 gg(GN/128, GM/128);   // (8, 32)
    gemm_f16x2<true><<<gg, 256, GEMM_SMEM>>>(Xh, Xl, Wqh, Wql, nullptr, Qh, Ql, 0.125f);
    gemm_f16x2<true><<<gg, 256, GEMM_SMEM>>>(Xh, Xl, Wkh, Wkl, nullptr, Kh, Kl, 1.0f);
    gemm_f16x2<true><<<gg, 256, GEMM_SMEM>>>(Xh, Xl, Wvh, Wvl, nullptr, Vh, Vl, 1.0f);

    flash_mma<<<dim3(SS/128, HH, BB), 256, FLASH_SMEM>>>(Qh, Ql, Kh, Kl, Vh, Vl, AOh, AOl);

    gemm_f16x2<false><<<gg, 256, GEMM_SMEM>>>(AOh, AOl, Woh, Wol, out, nullptr, nullptr, 1.0f);
}